// round 4
// baseline (speedup 1.0000x reference)
#include <cuda_runtime.h>

// out[b,o,d0,p1,p2,p3] = bias[o]
//   + sum_{i,c,k1,k2,k3} w[i,o,c,k1,k2,k3] * xp[b, L/26, L%26, p1+k1, p2+k2, p3+k3],  L=(d0+i)*32+c
// xp = x zero-padded by 1 on all four spatial dims (reference's reshape scrambles (Ci,D0p)).
// x(2,32,24,24,24,24) f32, w(3,64,32,3,3,3) f32, bias(64) f32, out(2,64,24,24,24,24) f32.

#define DDIM 24
#define CI 32
#define CO 64
#define OCB 16
#define NITER 96

typedef unsigned long long u64;

__device__ __forceinline__ u64 pack_dup(float a) {
    u64 r;
    unsigned ai = __float_as_uint(a);
    asm("mov.b64 %0, {%1, %1};" : "=l"(r) : "r"(ai));
    return r;
}
__device__ __forceinline__ void fma2(u64 &acc, u64 x, u64 wv) {
    asm("fma.rn.f32x2 %0, %1, %2, %0;" : "+l"(acc) : "l"(x), "l"(wv));
}
__device__ __forceinline__ void unpack2(u64 v, float &lo, float &hi) {
    unsigned l, h;
    asm("mov.b64 {%0, %1}, %2;" : "=r"(l), "=r"(h) : "l"(v));
    lo = __uint_as_float(l); hi = __uint_as_float(h);
}

__global__ __launch_bounds__(256, 2)
void conv4d_kernel(const float* __restrict__ x,
                   const float* __restrict__ w,
                   const float* __restrict__ bias,
                   float* __restrict__ out)
{
    // x values stored PRE-DUPLICATED as {v,v} u64 -> inner loop is pure LDS.64 + FFMA2
    __shared__ u64    xv[2][3 * 676];
    __shared__ float2 wv2[2][8 * 27];    // 8 oc-pairs x 27 taps

    const int blk = blockIdx.x;          // b*576 + d0*24 + d1
    const int d1  = blk % DDIM;
    const int t0  = blk / DDIM;
    const int d0  = t0 % DDIM;
    const int b   = t0 / DDIM;
    const int oc0 = blockIdx.y * OCB;

    const int tid = threadIdx.x;
    const int tx  = tid & 63;
    const int ty  = tid >> 6;
    const int rb  = tx >> 3;             // d2 block (rows rb*3..rb*3+2)
    const int cb  = tx & 7;              // d3 block (cols cb*3..cb*3+2)

    // ---- loop-invariant staging metadata (hoisted div/mod) ----
    int xoff[8]; unsigned xmask = 0;
    #pragma unroll
    for (int k = 0; k < 8; k++) {
        const int idx = tid + k * 256;
        const int s   = idx / 676, rem = idx - s * 676;
        const int r   = rem / 26,  c_  = rem - r * 26;
        const int e1  = d1 + s - 1, p2 = r - 1, p3 = c_ - 1;
        const bool ok = (idx < 2028) && (unsigned)e1 < DDIM &&
                        (unsigned)p2 < DDIM && (unsigned)p3 < DDIM;
        xoff[k] = e1 * 576 + p2 * 24 + p3;
        if (ok) xmask |= 1u << k;
    }
    int wgoff[2], wsts[2]; unsigned wok = 0;
    #pragma unroll
    for (int k = 0; k < 2; k++) {
        const int e = tid + k * 256;
        const int ocl = e / 27, t = e - ocl * 27;
        if (e < 432) wok |= 1u << k;
        wgoff[k] = (oc0 + ocl) * (CI * 27) + t;               // + i*55296 + c*27
        wsts[k]  = (ocl >> 1) * 54 + t * 2 + (ocl & 1);       // float index into wv2 row
    }

    u64 acc2[2][9];
    #pragma unroll
    for (int p = 0; p < 2; p++)
        #pragma unroll
        for (int q = 0; q < 9; q++) acc2[p][q] = 0ull;

    const int L0 = d0 * 32;

    // ---- stage L0 (i=0, c=0 since L0 % 32 == 0) ----
    {
        const int cin = L0 / 26, e0p = L0 % 26;
        const bool e0ok = (unsigned)(e0p - 1) < DDIM;
        const float* xrow = x + ((size_t)(b * CI + cin) * DDIM + (e0p - 1)) * 13824;
        float xr[8], wr[2];
        #pragma unroll
        for (int k = 0; k < 8; k++)
            xr[k] = (e0ok && ((xmask >> k) & 1)) ? __ldg(xrow + xoff[k]) : 0.0f;
        const float* wb = w;
        #pragma unroll
        for (int k = 0; k < 2; k++)
            wr[k] = ((wok >> k) & 1) ? __ldg(wb + wgoff[k]) : 0.0f;
        #pragma unroll
        for (int k = 0; k < 8; k++) {
            const int idx = tid + k * 256;
            if (idx < 2028) xv[0][idx] = pack_dup(xr[k]);
        }
        float* wf = (float*)wv2[0];
        #pragma unroll
        for (int k = 0; k < 2; k++)
            if ((wok >> k) & 1) wf[wsts[k]] = wr[k];
    }
    __syncthreads();

    int pb = 0;
    int ccin = L0 / 26, ce0p = L0 % 26;       // (cin, L%26) for CURRENT L
    for (int Lk = 0; Lk < NITER; Lk++) {
        const bool have_next = (Lk < NITER - 1);

        // ---- prefetch stage for L+1 into registers ----
        int ncin = ccin, ne0p = ce0p + 1;
        if (ne0p == 26) { ne0p = 0; ncin++; }
        float xr[8], wr[2];
        if (have_next) {
            const bool ne0ok = (unsigned)(ne0p - 1) < DDIM;
            const float* xrow = x + ((size_t)(b * CI + ncin) * DDIM + (ne0p - 1)) * 13824;
            #pragma unroll
            for (int k = 0; k < 8; k++)
                xr[k] = (ne0ok && ((xmask >> k) & 1)) ? __ldg(xrow + xoff[k]) : 0.0f;
            const int i_n = (Lk + 1) >> 5;               // (L+1)/32 - d0
            const int c_n = (L0 + Lk + 1) & 31;
            const float* wb = w + i_n * 55296 + c_n * 27;
            #pragma unroll
            for (int k = 0; k < 2; k++)
                wr[k] = ((wok >> k) & 1) ? __ldg(wb + wgoff[k]) : 0.0f;
        }

        // ---- compute current L from buffer pb ----
        if ((unsigned)(ce0p - 1) < DDIM) {
            #pragma unroll
            for (int k1 = 0; k1 < 3; k1++) {
                u64 wp0[9], wp1[9];
                const u64* wr0 = (const u64*)&wv2[pb][(ty * 2 + 0) * 27 + k1 * 9];
                const u64* wr1 = (const u64*)&wv2[pb][(ty * 2 + 1) * 27 + k1 * 9];
                #pragma unroll
                for (int t = 0; t < 9; t++) { wp0[t] = wr0[t]; wp1[t] = wr1[t]; }

                const u64* xsl = &xv[pb][k1 * 676 + rb * 78 + cb * 3];
                #pragma unroll
                for (int r = 0; r < 5; r++) {
                    #pragma unroll
                    for (int s = 0; s < 5; s++) {
                        const u64 x2 = xsl[r * 26 + s];   // LDS.64, pre-duplicated
                        #pragma unroll
                        for (int k2 = (r > 2 ? r - 2 : 0); k2 <= (r < 2 ? r : 2); k2++) {
                            #pragma unroll
                            for (int k3 = (s > 2 ? s - 2 : 0); k3 <= (s < 2 ? s : 2); k3++) {
                                const int pos = (r - k2) * 3 + (s - k3);
                                const int t   = k2 * 3 + k3;
                                fma2(acc2[0][pos], x2, wp0[t]);
                                fma2(acc2[1][pos], x2, wp1[t]);
                            }
                        }
                    }
                }
            }
        }

        // ---- commit prefetched stage, flip ----
        if (have_next) {
            #pragma unroll
            for (int k = 0; k < 8; k++) {
                const int idx = tid + k * 256;
                if (idx < 2028) xv[pb ^ 1][idx] = pack_dup(xr[k]);
            }
            float* wf = (float*)wv2[pb ^ 1];
            #pragma unroll
            for (int k = 0; k < 2; k++)
                if ((wok >> k) & 1) wf[wsts[k]] = wr[k];
            __syncthreads();
        }
        pb ^= 1;
        ccin = ncin; ce0p = ne0p;
    }

    // ---- epilogue: unpack, add bias, store ----
    #pragma unroll
    for (int p = 0; p < 2; p++) {
        const int oce = oc0 + ty * 4 + p * 2;       // even oc of the pair
        const float bv0 = bias[oce];
        const float bv1 = bias[oce + 1];
        const size_t ob0 = ((size_t)(b * CO + oce) * 576 + d0 * 24 + d1) * 576;
        const size_t ob1 = ob0 + (size_t)331776;    // next oc: +576*576
        #pragma unroll
        for (int ii = 0; ii < 3; ii++) {
            #pragma unroll
            for (int jj = 0; jj < 3; jj++) {
                float lo, hi;
                unpack2(acc2[p][ii * 3 + jj], lo, hi);
                const int po = (rb * 3 + ii) * 24 + cb * 3 + jj;
                out[ob0 + po] = lo + bv0;
                out[ob1 + po] = hi + bv1;
            }
        }
    }
}

extern "C" void kernel_launch(void* const* d_in, const int* in_sizes, int n_in,
                              void* d_out, int out_size)
{
    const float* x = nullptr;
    const float* w = nullptr;
    const float* bias = nullptr;
    for (int k = 0; k < n_in; k++) {
        if (in_sizes[k] == 2 * 32 * 24 * 24 * 24 * 24) x    = (const float*)d_in[k];
        else if (in_sizes[k] == 3 * 64 * 32 * 27)      w    = (const float*)d_in[k];
        else if (in_sizes[k] == 64)                    bias = (const float*)d_in[k];
    }
    float* out = (float*)d_out;

    dim3 grid(2 * 24 * 24, CO / OCB);   // (1152, 4)
    dim3 block(256);
    conv4d_kernel<<<grid, block>>>(x, w, bias, out);
}

// round 5
// speedup vs baseline: 1.1989x; 1.1989x over previous
#include <cuda_runtime.h>

// out[b,o,d0,p1,p2,p3] = bias[o]
//   + sum_{i,c,k1,k2,k3} w[i,o,c,k1,k2,k3] * xp[b, L/26, L%26, p1+k1, p2+k2, p3+k3],  L=(d0+i)*32+c
// xp = x zero-padded by 1 on all four spatial dims (reference's reshape scrambles (Ci,D0p)).
// x(2,32,24,24,24,24) f32, w(3,64,32,3,3,3) f32, bias(64) f32, out(2,64,24,24,24,24) f32.

#define DDIM 24
#define CI 32
#define CO 64
#define OCB 16
#define NITER 96
#define SLOTS 6
#define XSL 2028            // 3*676 floats per L
#define WSL 216             // float2 per L (16 oc x 27 taps interleaved as 8 pairs)

typedef unsigned long long u64;

__device__ __forceinline__ u64 pack_dup(float a) {
    u64 r;
    unsigned ai = __float_as_uint(a);
    asm("mov.b64 %0, {%1, %1};" : "=l"(r) : "r"(ai));
    return r;
}
__device__ __forceinline__ void fma2(u64 &acc, u64 x, u64 wv) {
    asm("fma.rn.f32x2 %0, %1, %2, %0;" : "+l"(acc) : "l"(x), "l"(wv));
}
__device__ __forceinline__ void unpack2(u64 v, float &lo, float &hi) {
    unsigned l, h;
    asm("mov.b64 {%0, %1}, %2;" : "=r"(l), "=r"(h) : "l"(v));
    lo = __uint_as_float(l); hi = __uint_as_float(h);
}
__device__ __forceinline__ void cpasync4(const float* smem_dst, const float* gsrc, unsigned srcsz) {
    unsigned a = (unsigned)__cvta_generic_to_shared(smem_dst);
    asm volatile("cp.async.ca.shared.global [%0], [%1], 4, %2;"
                 :: "r"(a), "l"(gsrc), "r"(srcsz) : "memory");
}
__device__ __forceinline__ void cp_commit() {
    asm volatile("cp.async.commit_group;" ::: "memory");
}
__device__ __forceinline__ void cp_wait2() {
    asm volatile("cp.async.wait_group 2;" ::: "memory");
}

// stage one L into its ring slot via cp.async (zfill for padding / invalid frames)
__device__ __forceinline__ void stage_L(int Lk, int L0, int b,
                                        const float* __restrict__ x,
                                        const float* __restrict__ w,
                                        const int* xoff, unsigned xmask,
                                        const int* wgoff, const int* wsts, unsigned wok,
                                        float* xs, float2* wv2, int tid)
{
    if (Lk < NITER) {
        const int slot = Lk % SLOTS;
        const int Labs = L0 + Lk;
        const int cin  = Labs / 26;
        const int e0p  = Labs - cin * 26;
        const bool fok = (unsigned)(e0p - 1) < (unsigned)DDIM;
        const float* xrow = x + ((size_t)(b * CI + cin) * DDIM + (fok ? e0p - 1 : 0)) * 13824;
        float* xd = xs + slot * XSL;
        #pragma unroll
        for (int k = 0; k < 8; k++) {
            const int idx = tid + k * 256;
            if (idx < XSL) {
                const unsigned sz = (fok && ((xmask >> k) & 1)) ? 4u : 0u;
                cpasync4(xd + idx, xrow + xoff[k], sz);
            }
        }
        const int i = Lk >> 5;
        const int c = Labs & 31;
        const float* wb = w + i * 55296 + c * 27;
        float* wd = (float*)(wv2 + slot * WSL);
        #pragma unroll
        for (int k = 0; k < 2; k++)
            if ((wok >> k) & 1) cpasync4(wd + wsts[k], wb + wgoff[k], 4u);
    }
    cp_commit();   // always commit (possibly empty) to keep group counting uniform
}

// compute one L from ring slot: 486 FFMA2 per thread
__device__ __forceinline__ void compute_L(const float* xsl0, const float2* wslot,
                                          int ty, int rb, int cb, u64 acc2[2][9])
{
    #pragma unroll
    for (int k1 = 0; k1 < 3; k1++) {
        u64 wp0[9], wp1[9];
        const u64* wr0 = (const u64*)&wslot[0] + (size_t)((ty * 2 + 0) * 27 + k1 * 9);
        const u64* wr1 = (const u64*)&wslot[0] + (size_t)((ty * 2 + 1) * 27 + k1 * 9);
        #pragma unroll
        for (int t = 0; t < 9; t++) { wp0[t] = wr0[t]; wp1[t] = wr1[t]; }

        const float* xsl = xsl0 + k1 * 676 + rb * 78 + cb * 3;
        #pragma unroll
        for (int r = 0; r < 5; r++) {
            #pragma unroll
            for (int s = 0; s < 5; s++) {
                const u64 x2 = pack_dup(xsl[r * 26 + s]);
                #pragma unroll
                for (int k2 = (r > 2 ? r - 2 : 0); k2 <= (r < 2 ? r : 2); k2++) {
                    #pragma unroll
                    for (int k3 = (s > 2 ? s - 2 : 0); k3 <= (s < 2 ? s : 2); k3++) {
                        const int pos = (r - k2) * 3 + (s - k3);
                        const int t   = k2 * 3 + k3;
                        fma2(acc2[0][pos], x2, wp0[t]);
                        fma2(acc2[1][pos], x2, wp1[t]);
                    }
                }
            }
        }
    }
}

__global__ __launch_bounds__(256, 2)
void conv4d_kernel(const float* __restrict__ x,
                   const float* __restrict__ w,
                   const float* __restrict__ bias,
                   float* __restrict__ out)
{
    extern __shared__ float smem_dyn[];
    float*  xs  = smem_dyn;                          // SLOTS * 2028 floats
    float2* wv2 = (float2*)(smem_dyn + SLOTS * XSL); // SLOTS * 216 float2

    const int blk = blockIdx.x;          // b*576 + d0*24 + d1
    const int d1  = blk % DDIM;
    const int t0  = blk / DDIM;
    const int d0  = t0 % DDIM;
    const int b   = t0 / DDIM;
    const int oc0 = blockIdx.y * OCB;

    const int tid = threadIdx.x;
    const int tx  = tid & 63;
    const int ty  = tid >> 6;
    const int rb  = tx >> 3;             // d2 block (rows rb*3..rb*3+2)
    const int cb  = tx & 7;              // d3 block (cols cb*3..cb*3+2)

    // ---- loop-invariant staging metadata ----
    int xoff[8]; unsigned xmask = 0;
    #pragma unroll
    for (int k = 0; k < 8; k++) {
        const int idx = tid + k * 256;
        const int s   = idx / 676, rem = idx - s * 676;
        const int r   = rem / 26,  c_  = rem - r * 26;
        const int e1  = d1 + s - 1, p2 = r - 1, p3 = c_ - 1;
        const bool ok = (idx < XSL) && (unsigned)e1 < DDIM &&
                        (unsigned)p2 < DDIM && (unsigned)p3 < DDIM;
        xoff[k] = ok ? (e1 * 576 + p2 * 24 + p3) : 0;
        if (ok) xmask |= 1u << k;
    }
    int wgoff[2], wsts[2]; unsigned wok = 0;
    #pragma unroll
    for (int k = 0; k < 2; k++) {
        const int e = tid + k * 256;
        const int ocl = e / 27, t = e - ocl * 27;
        if (e < 432) wok |= 1u << k;
        wgoff[k] = (oc0 + ocl) * (CI * 27) + t;               // + i*55296 + c*27
        wsts[k]  = (ocl >> 1) * 54 + t * 2 + (ocl & 1);       // float index into slot
    }

    u64 acc2[2][9];
    #pragma unroll
    for (int p = 0; p < 2; p++)
        #pragma unroll
        for (int q = 0; q < 9; q++) acc2[p][q] = 0ull;

    const int L0 = d0 * 32;

    // ---- prologue: stage L0..L3 (4 groups in flight) ----
    #pragma unroll
    for (int Lk = 0; Lk < 4; Lk++)
        stage_L(Lk, L0, b, x, w, xoff, xmask, wgoff, wsts, wok, xs, wv2, tid);

    // ---- main loop: 48 epochs of 2 L each, one barrier per epoch ----
    for (int e = 0; e < NITER / 2; e++) {
        const int Lk = 2 * e;
        cp_wait2();           // L=Lk, Lk+1 complete (2 newer groups may be pending)
        __syncthreads();

        // issue prefetch for Lk+4, Lk+5 (their slots were consumed in epoch e-1)
        stage_L(Lk + 4, L0, b, x, w, xoff, xmask, wgoff, wsts, wok, xs, wv2, tid);
        stage_L(Lk + 5, L0, b, x, w, xoff, xmask, wgoff, wsts, wok, xs, wv2, tid);

        // compute the two ready L values
        #pragma unroll
        for (int t = 0; t < 2; t++) {
            const int La   = L0 + Lk + t;
            const int e0p  = La % 26;
            if ((unsigned)(e0p - 1) < (unsigned)DDIM) {
                const int slot = (Lk + t) % SLOTS;
                compute_L(xs + slot * XSL, wv2 + slot * WSL, ty, rb, cb, acc2);
            }
        }
    }

    // ---- epilogue: unpack, add bias, store ----
    #pragma unroll
    for (int p = 0; p < 2; p++) {
        const int oce = oc0 + ty * 4 + p * 2;       // even oc of the pair
        const float bv0 = bias[oce];
        const float bv1 = bias[oce + 1];
        const size_t ob0 = ((size_t)(b * CO + oce) * 576 + d0 * 24 + d1) * 576;
        const size_t ob1 = ob0 + (size_t)331776;    // next oc: +576*576
        #pragma unroll
        for (int ii = 0; ii < 3; ii++) {
            #pragma unroll
            for (int jj = 0; jj < 3; jj++) {
                float lo, hi;
                unpack2(acc2[p][ii * 3 + jj], lo, hi);
                const int po = (rb * 3 + ii) * 24 + cb * 3 + jj;
                out[ob0 + po] = lo + bv0;
                out[ob1 + po] = hi + bv1;
            }
        }
    }
}

extern "C" void kernel_launch(void* const* d_in, const int* in_sizes, int n_in,
                              void* d_out, int out_size)
{
    const float* x = nullptr;
    const float* w = nullptr;
    const float* bias = nullptr;
    for (int k = 0; k < n_in; k++) {
        if (in_sizes[k] == 2 * 32 * 24 * 24 * 24 * 24) x    = (const float*)d_in[k];
        else if (in_sizes[k] == 3 * 64 * 32 * 27)      w    = (const float*)d_in[k];
        else if (in_sizes[k] == 64)                    bias = (const float*)d_in[k];
    }
    float* out = (float*)d_out;

    const int smem_bytes = SLOTS * XSL * 4 + SLOTS * WSL * 8;  // 59040
    cudaFuncSetAttribute(conv4d_kernel, cudaFuncAttributeMaxDynamicSharedMemorySize, smem_bytes);

    dim3 grid(2 * 24 * 24, CO / OCB);   // (1152, 4)
    dim3 block(256);
    conv4d_kernel<<<grid, block, smem_bytes>>>(x, w, bias, out);
}